// round 5
// baseline (speedup 1.0000x reference)
#include <cuda_runtime.h>

#define Bsz 4
#define Sq  2048
#define Emb 768
#define NH  12
#define HD  64

// Scratch for Q, K, V in [B, H, S, D] layout (25.2 MB each)
__device__ float g_Q[(size_t)Bsz * NH * Sq * HD];
__device__ float g_K[(size_t)Bsz * NH * Sq * HD];
__device__ float g_V[(size_t)Bsz * NH * Sq * HD];

// ---------------------------------------------------------------------------
// Kernel 1: fused QKV projection.  Y = X @ W^T + b, written to [B,H,S,D].
// Grid: x = 18 column tiles (6 per matrix: Q,K,V), y = 64 row tiles of 128 tokens.
// Block: 256 threads, each computes an 8x8 micro-tile. K-tile = 16.
// ---------------------------------------------------------------------------
__global__ __launch_bounds__(256)
void qkv_kernel(const float* __restrict__ X,
                const float* __restrict__ Wq, const float* __restrict__ bq,
                const float* __restrict__ Wk, const float* __restrict__ bk,
                const float* __restrict__ Wv, const float* __restrict__ bv)
{
    __shared__ float Xs[16][132];   // Xs[k][m]  (transposed, padded)
    __shared__ float Ws[16][132];   // Ws[k][n]

    const int tid = threadIdx.x;
    const int tx  = tid & 15;
    const int ty  = tid >> 4;

    const int bx    = blockIdx.x;            // 0..17
    const int row0  = blockIdx.y * 128;      // token tile base
    const int which = bx / 6;                // 0=Q, 1=K, 2=V
    const int o0    = (bx % 6) * 128;        // output-feature tile base

    const float* W    = (which == 0) ? Wq : (which == 1) ? Wk : Wv;
    const float* bias = (which == 0) ? bq : (which == 1) ? bk : bv;
    float*       dst  = (which == 0) ? g_Q : (which == 1) ? g_K : g_V;
    const float scale = (which == 0) ? 0.125f : 1.0f;   // 1/sqrt(64) folded into Q

    float c[8][8];
    #pragma unroll
    for (int i = 0; i < 8; i++)
        #pragma unroll
        for (int j = 0; j < 8; j++) c[i][j] = 0.f;

    const int lm = tid >> 2;        // 0..63
    const int lk = (tid & 3) * 4;   // 0,4,8,12

    for (int kt = 0; kt < Emb / 16; kt++) {
        const int k0 = kt * 16;
        #pragma unroll
        for (int r = 0; r < 2; r++) {
            const int m = lm + r * 64;
            float4 xv = *(const float4*)&X[(size_t)(row0 + m) * Emb + k0 + lk];
            Xs[lk + 0][m] = xv.x; Xs[lk + 1][m] = xv.y;
            Xs[lk + 2][m] = xv.z; Xs[lk + 3][m] = xv.w;
            float4 wv = *(const float4*)&W[(size_t)(o0 + m) * Emb + k0 + lk];
            Ws[lk + 0][m] = wv.x; Ws[lk + 1][m] = wv.y;
            Ws[lk + 2][m] = wv.z; Ws[lk + 3][m] = wv.w;
        }
        __syncthreads();

        #pragma unroll
        for (int k = 0; k < 16; k++) {
            float a[8], bb[8];
            *(float4*)&a[0]  = *(const float4*)&Xs[k][ty * 8];
            *(float4*)&a[4]  = *(const float4*)&Xs[k][ty * 8 + 4];
            *(float4*)&bb[0] = *(const float4*)&Ws[k][tx * 8];
            *(float4*)&bb[4] = *(const float4*)&Ws[k][tx * 8 + 4];
            #pragma unroll
            for (int i = 0; i < 8; i++)
                #pragma unroll
                for (int j = 0; j < 8; j++)
                    c[i][j] = fmaf(a[i], bb[j], c[i][j]);
        }
        __syncthreads();
    }

    // Epilogue: bias, scale, scatter to [B,H,S,D]
    #pragma unroll
    for (int i = 0; i < 8; i++) {
        const int tok = row0 + ty * 8 + i;
        const int b   = tok >> 11;       // /2048
        const int s   = tok & 2047;
        #pragma unroll
        for (int j = 0; j < 8; j += 4) {
            const int o = o0 + tx * 8 + j;
            const int h = o >> 6;
            const int d = o & 63;
            float4 bv4 = *(const float4*)&bias[o];
            float4 v;
            v.x = (c[i][j + 0] + bv4.x) * scale;
            v.y = (c[i][j + 1] + bv4.y) * scale;
            v.z = (c[i][j + 2] + bv4.z) * scale;
            v.w = (c[i][j + 3] + bv4.w) * scale;
            *(float4*)&dst[((((size_t)b * NH + h) * Sq) + s) * HD + d] = v;
        }
    }
}

// ---------------------------------------------------------------------------
// Kernel 2: flash attention (fp32, online softmax).
// Grid: (S/64 q-tiles, H, B). Block: 256 threads (16x16), 4x4 micro-tiles.
// Smem: Qs/Ks d-major [64][68], Vs k-major [64][68], Ss = S^T [k][q] [64][68].
// ---------------------------------------------------------------------------
#define SPAD 68
#define ATTN_SMEM_BYTES ((4 * 64 * SPAD + 3 * 64) * 4)

__global__ __launch_bounds__(256)
void attn_kernel(const float* __restrict__ am,   // [B,1,1,S]
                 const float* __restrict__ dm,   // [B,1,S,S]
                 float* __restrict__ out)        // [B,S,E]
{
    extern __shared__ float sm[];
    float* Qs   = sm;                 // [d][q]
    float* Ks   = Qs + 64 * SPAD;     // [d][k]
    float* Vs   = Ks + 64 * SPAD;     // [k][d]
    float* Ss   = Vs + 64 * SPAD;     // [k][q]  (S transposed, then P)
    float* mrow = Ss + 64 * SPAD;     // [64]
    float* lrow = mrow + 64;          // [64]
    float* arow = lrow + 64;          // [64]

    const int tid = threadIdx.x;
    const int tx  = tid & 15;
    const int ty  = tid >> 4;
    const int q0  = blockIdx.x * 64;
    const int h   = blockIdx.y;
    const int b   = blockIdx.z;

    const float* Qg = g_Q + ((size_t)b * NH + h) * Sq * HD;
    const float* Kg = g_K + ((size_t)b * NH + h) * Sq * HD;
    const float* Vg = g_V + ((size_t)b * NH + h) * Sq * HD;

    // Load Q tile transposed into Qs[d][q]
    {
        const int q = tid >> 2;
        #pragma unroll
        for (int r = 0; r < 4; r++) {
            const int d0 = (tid & 3) * 16 + r * 4;
            float4 v = *(const float4*)&Qg[(size_t)(q0 + q) * HD + d0];
            Qs[(d0 + 0) * SPAD + q] = v.x;
            Qs[(d0 + 1) * SPAD + q] = v.y;
            Qs[(d0 + 2) * SPAD + q] = v.z;
            Qs[(d0 + 3) * SPAD + q] = v.w;
        }
    }
    if (tid < 64) { mrow[tid] = -1e30f; lrow[tid] = 0.f; }

    float o[4][4];
    #pragma unroll
    for (int i = 0; i < 4; i++)
        #pragma unroll
        for (int j = 0; j < 4; j++) o[i][j] = 0.f;

    __syncthreads();

    for (int kt = 0; kt < Sq / 64; kt++) {
        const int k0 = kt * 64;

        // Load K (transposed) and V (natural)
        {
            const int kk = tid >> 2;
            #pragma unroll
            for (int r = 0; r < 4; r++) {
                const int d0 = (tid & 3) * 16 + r * 4;
                float4 kv = *(const float4*)&Kg[(size_t)(k0 + kk) * HD + d0];
                Ks[(d0 + 0) * SPAD + kk] = kv.x;
                Ks[(d0 + 1) * SPAD + kk] = kv.y;
                Ks[(d0 + 2) * SPAD + kk] = kv.z;
                Ks[(d0 + 3) * SPAD + kk] = kv.w;
                float4 vv = *(const float4*)&Vg[(size_t)(k0 + kk) * HD + d0];
                *(float4*)&Vs[kk * SPAD + d0] = vv;
            }
        }
        __syncthreads();

        // S = Q K^T  (Q already scaled by 1/sqrt(D)), add both masks
        float s[4][4];
        #pragma unroll
        for (int i = 0; i < 4; i++)
            #pragma unroll
            for (int j = 0; j < 4; j++) s[i][j] = 0.f;

        #pragma unroll 8
        for (int d = 0; d < HD; d++) {
            float4 q4 = *(const float4*)&Qs[d * SPAD + 4 * ty];
            float4 k4 = *(const float4*)&Ks[d * SPAD + 4 * tx];
            const float qa[4] = {q4.x, q4.y, q4.z, q4.w};
            const float ka[4] = {k4.x, k4.y, k4.z, k4.w};
            #pragma unroll
            for (int i = 0; i < 4; i++)
                #pragma unroll
                for (int j = 0; j < 4; j++)
                    s[i][j] = fmaf(qa[i], ka[j], s[i][j]);
        }

        {
            float4 amv = *(const float4*)&am[(size_t)b * Sq + k0 + 4 * tx];
            const float ama[4] = {amv.x, amv.y, amv.z, amv.w};
            #pragma unroll
            for (int i = 0; i < 4; i++) {
                const int qg = q0 + 4 * ty + i;
                float4 dmv = *(const float4*)&dm[((size_t)b * Sq + qg) * Sq + k0 + 4 * tx];
                const float dma[4] = {dmv.x, dmv.y, dmv.z, dmv.w};
                #pragma unroll
                for (int j = 0; j < 4; j++) s[i][j] += ama[j] + dma[j];
            }
            // Write S transposed: Ss[k][q]
            #pragma unroll
            for (int j = 0; j < 4; j++) {
                float4 v = make_float4(s[0][j], s[1][j], s[2][j], s[3][j]);
                *(float4*)&Ss[(4 * tx + j) * SPAD + 4 * ty] = v;
            }
        }
        __syncthreads();

        // Online softmax: 4 threads per q-row, 16 keys each
        {
            const int q    = tid >> 2;
            const int part = tid & 3;
            float lmax = -1e30f;
            #pragma unroll
            for (int kk = 0; kk < 16; kk++)
                lmax = fmaxf(lmax, Ss[(part * 16 + kk) * SPAD + q]);
            lmax = fmaxf(lmax, __shfl_xor_sync(0xffffffffu, lmax, 1));
            lmax = fmaxf(lmax, __shfl_xor_sync(0xffffffffu, lmax, 2));

            const float mold = mrow[q];
            const float mnew = fmaxf(mold, lmax);
            float lsum = 0.f;
            #pragma unroll
            for (int kk = 0; kk < 16; kk++) {
                const int idx = (part * 16 + kk) * SPAD + q;
                float p = __expf(Ss[idx] - mnew);
                Ss[idx] = p;
                lsum += p;
            }
            lsum += __shfl_xor_sync(0xffffffffu, lsum, 1);
            lsum += __shfl_xor_sync(0xffffffffu, lsum, 2);
            if (part == 0) {
                const float alpha = __expf(mold - mnew);
                lrow[q] = lrow[q] * alpha + lsum;
                mrow[q] = mnew;
                arow[q] = alpha;
            }
        }
        __syncthreads();

        // O = O * alpha + P @ V
        {
            float al[4];
            #pragma unroll
            for (int i = 0; i < 4; i++) al[i] = arow[4 * ty + i];
            #pragma unroll
            for (int i = 0; i < 4; i++)
                #pragma unroll
                for (int j = 0; j < 4; j++) o[i][j] *= al[i];

            #pragma unroll 8
            for (int kk = 0; kk < 64; kk++) {
                float4 p4 = *(const float4*)&Ss[kk * SPAD + 4 * ty];
                float4 v4 = *(const float4*)&Vs[kk * SPAD + 4 * tx];
                const float pa[4] = {p4.x, p4.y, p4.z, p4.w};
                const float va[4] = {v4.x, v4.y, v4.z, v4.w};
                #pragma unroll
                for (int i = 0; i < 4; i++)
                    #pragma unroll
                    for (int j = 0; j < 4; j++)
                        o[i][j] = fmaf(pa[i], va[j], o[i][j]);
            }
        }
        __syncthreads();
    }

    // Normalize and write: out[b][q][h*64 + d]
    #pragma unroll
    for (int i = 0; i < 4; i++) {
        const int qg  = q0 + 4 * ty + i;
        const float inv = 1.0f / lrow[4 * ty + i];
        float4 v = make_float4(o[i][0] * inv, o[i][1] * inv,
                               o[i][2] * inv, o[i][3] * inv);
        *(float4*)&out[((size_t)b * Sq + qg) * Emb + h * HD + 4 * tx] = v;
    }
}

// ---------------------------------------------------------------------------
extern "C" void kernel_launch(void* const* d_in, const int* in_sizes, int n_in,
                              void* d_out, int out_size)
{
    const float* X  = (const float*)d_in[0];  // hidden_states [4,2048,768]
    const float* am = (const float*)d_in[1];  // attention_mask [4,1,1,2048]
    const float* dm = (const float*)d_in[2];  // domain_attn_mask [4,1,2048,2048]
    const float* Wq = (const float*)d_in[3];
    const float* bq = (const float*)d_in[4];
    const float* Wk = (const float*)d_in[5];
    const float* bk = (const float*)d_in[6];
    const float* Wv = (const float*)d_in[7];
    const float* bv = (const float*)d_in[8];
    float* out = (float*)d_out;

    qkv_kernel<<<dim3(18, 64), 256>>>(X, Wq, bq, Wk, bk, Wv, bv);

    cudaFuncSetAttribute(attn_kernel,
                         cudaFuncAttributeMaxDynamicSharedMemorySize,
                         ATTN_SMEM_BYTES);
    attn_kernel<<<dim3(Sq / 64, NH, Bsz), 256, ATTN_SMEM_BYTES>>>(am, dm, out);
}

// round 6
// speedup vs baseline: 2.3136x; 2.3136x over previous
#include <cuda_runtime.h>

#define Bsz 4
#define Sq  2048
#define Emb 768
#define NH  12
#define HD  64

// Scratch for Q, K, V in [B, H, S, D] layout
__device__ float g_Q[(size_t)Bsz * NH * Sq * HD];
__device__ float g_K[(size_t)Bsz * NH * Sq * HD];
__device__ float g_V[(size_t)Bsz * NH * Sq * HD];

// ---------------------------------------------------------------------------
// TF32 helpers
// ---------------------------------------------------------------------------
__device__ __forceinline__ unsigned f2tf(float x) {
    unsigned r;
    asm("cvt.rna.tf32.f32 %0, %1;" : "=r"(r) : "f"(x));
    return r;
}

__device__ __forceinline__ void mma_tf32(float* d, const unsigned* a, const unsigned* b) {
    asm volatile(
        "mma.sync.aligned.m16n8k8.row.col.f32.tf32.tf32.f32 "
        "{%0,%1,%2,%3}, {%4,%5,%6,%7}, {%8,%9}, {%0,%1,%2,%3};"
        : "+f"(d[0]), "+f"(d[1]), "+f"(d[2]), "+f"(d[3])
        : "r"(a[0]), "r"(a[1]), "r"(a[2]), "r"(a[3]), "r"(b[0]), "r"(b[1]));
}

// ---------------------------------------------------------------------------
// Kernel 1: fused QKV projection via TF32 mma. Y = X @ W^T + b -> [B,H,S,D].
// Grid: x = 18 (6 n-tiles each for Q,K,V), y = 64 token tiles of 128.
// Block 256 = 8 warps as 4(m) x 2(n); warp tile 32m x 64n; K-tile 32.
// ---------------------------------------------------------------------------
#define XPAD 36

__global__ __launch_bounds__(256, 2)
void qkv_kernel(const float* __restrict__ X,
                const float* __restrict__ Wq, const float* __restrict__ bq,
                const float* __restrict__ Wk, const float* __restrict__ bk,
                const float* __restrict__ Wv, const float* __restrict__ bv)
{
    __shared__ float Xs[128][XPAD];   // [token][k]  (tf32 bits)
    __shared__ float Ws[128][XPAD];   // [outfeat][k]

    const int tid = threadIdx.x;
    const int w   = tid >> 5;
    const int l   = tid & 31;
    const int wm  = w >> 1;        // 0..3
    const int wn  = w & 1;         // 0..1
    const int lg  = l >> 2;        // 0..7
    const int lt  = l & 3;         // 0..3

    const int bx    = blockIdx.x;
    const int row0  = blockIdx.y * 128;
    const int which = bx / 6;
    const int o0    = (bx % 6) * 128;

    const float* W    = (which == 0) ? Wq : (which == 1) ? Wk : Wv;
    const float* bias = (which == 0) ? bq : (which == 1) ? bk : bv;
    float*       dst  = (which == 0) ? g_Q : (which == 1) ? g_K : g_V;
    const float scale = (which == 0) ? 0.125f : 1.0f;   // 1/sqrt(64) into Q

    float acc[2][8][4];
    #pragma unroll
    for (int mt = 0; mt < 2; mt++)
        #pragma unroll
        for (int nt = 0; nt < 8; nt++)
            #pragma unroll
            for (int j = 0; j < 4; j++) acc[mt][nt][j] = 0.f;

    const int cr = tid >> 1;            // 0..127
    const int cc = (tid & 1) * 16;      // 0 or 16

    for (int kt = 0; kt < Emb / 32; kt++) {
        const int k0 = kt * 32;
        #pragma unroll
        for (int u = 0; u < 4; u++) {
            float4 xv = *(const float4*)&X[(size_t)(row0 + cr) * Emb + k0 + cc + 4 * u];
            float4 xt;
            xt.x = __uint_as_float(f2tf(xv.x)); xt.y = __uint_as_float(f2tf(xv.y));
            xt.z = __uint_as_float(f2tf(xv.z)); xt.w = __uint_as_float(f2tf(xv.w));
            *(float4*)&Xs[cr][cc + 4 * u] = xt;
            float4 wv = *(const float4*)&W[(size_t)(o0 + cr) * Emb + k0 + cc + 4 * u];
            float4 wt;
            wt.x = __uint_as_float(f2tf(wv.x)); wt.y = __uint_as_float(f2tf(wv.y));
            wt.z = __uint_as_float(f2tf(wv.z)); wt.w = __uint_as_float(f2tf(wv.w));
            *(float4*)&Ws[cr][cc + 4 * u] = wt;
        }
        __syncthreads();

        #pragma unroll
        for (int ks = 0; ks < 4; ks++) {
            unsigned a[2][4];
            #pragma unroll
            for (int mt = 0; mt < 2; mt++) {
                const int rb = 32 * wm + 16 * mt + lg;
                a[mt][0] = __float_as_uint(Xs[rb    ][8 * ks + lt    ]);
                a[mt][1] = __float_as_uint(Xs[rb + 8][8 * ks + lt    ]);
                a[mt][2] = __float_as_uint(Xs[rb    ][8 * ks + lt + 4]);
                a[mt][3] = __float_as_uint(Xs[rb + 8][8 * ks + lt + 4]);
            }
            #pragma unroll
            for (int nt = 0; nt < 8; nt++) {
                const int br = 64 * wn + 8 * nt + lg;
                unsigned bb[2];
                bb[0] = __float_as_uint(Ws[br][8 * ks + lt    ]);
                bb[1] = __float_as_uint(Ws[br][8 * ks + lt + 4]);
                mma_tf32(acc[0][nt], a[0], bb);
                mma_tf32(acc[1][nt], a[1], bb);
            }
        }
        __syncthreads();
    }

    // Epilogue: bias, scale, scatter to [B,H,S,D]
    #pragma unroll
    for (int nt = 0; nt < 8; nt++) {
        const int nl = 64 * wn + 8 * nt + 2 * lt;
        const int o  = o0 + nl;
        const int h  = o >> 6;
        const int d  = o & 63;
        float2 bv2 = *(const float2*)&bias[o];
        #pragma unroll
        for (int mt = 0; mt < 2; mt++) {
            #pragma unroll
            for (int i = 0; i < 2; i++) {
                const int tok = row0 + 32 * wm + 16 * mt + lg + 8 * i;
                const int b   = tok >> 11;
                const int s   = tok & 2047;
                float2 r;
                r.x = (acc[mt][nt][2 * i    ] + bv2.x) * scale;
                r.y = (acc[mt][nt][2 * i + 1] + bv2.y) * scale;
                *(float2*)&dst[(((size_t)b * NH + h) * Sq + s) * HD + d] = r;
            }
        }
    }
}

// ---------------------------------------------------------------------------
// Kernel 2: TF32 flash attention.
// Grid (16 q-tiles, 12 h, 4 b); block 256 (8 warps, 16 q-rows each).
// q-tile 128, k-tile 64. Smem: Ks[64][68], Vs[64][68], Ps[128][68].
// ---------------------------------------------------------------------------
#define SP 68
#define ATTN_SMEM ((64 + 64 + 128) * SP * 4)

__global__ __launch_bounds__(256, 1)
void attn_kernel(const float* __restrict__ am,   // [B,1,1,S]
                 const float* __restrict__ dm,   // [B,1,S,S]
                 float* __restrict__ out)        // [B,S,E]
{
    extern __shared__ float sm[];
    float (*Ks)[SP] = (float(*)[SP])sm;
    float (*Vs)[SP] = (float(*)[SP])(sm + 64 * SP);
    float (*Ps)[SP] = (float(*)[SP])(sm + 128 * SP);

    const int tid = threadIdx.x;
    const int w   = tid >> 5;
    const int l   = tid & 31;
    const int lg  = l >> 2;   // 0..7
    const int lt  = l & 3;    // 0..3

    const int q0 = blockIdx.x * 128;
    const int h  = blockIdx.y;
    const int b  = blockIdx.z;

    const float* Qg = g_Q + ((size_t)b * NH + h) * Sq * HD;
    const float* Kg = g_K + ((size_t)b * NH + h) * Sq * HD;
    const float* Vg = g_V + ((size_t)b * NH + h) * Sq * HD;

    const int qr = q0 + 16 * w + lg;     // this thread's base query row (global)
    const int pr = 16 * w + lg;          // base row within Ps

    // Q fragments in registers for the whole block (Q already scaled 1/8)
    unsigned qa[8][4];
    #pragma unroll
    for (int ks = 0; ks < 8; ks++) {
        qa[ks][0] = f2tf(Qg[(size_t)(qr    ) * HD + 8 * ks + lt    ]);
        qa[ks][1] = f2tf(Qg[(size_t)(qr + 8) * HD + 8 * ks + lt    ]);
        qa[ks][2] = f2tf(Qg[(size_t)(qr    ) * HD + 8 * ks + lt + 4]);
        qa[ks][3] = f2tf(Qg[(size_t)(qr + 8) * HD + 8 * ks + lt + 4]);
    }

    float o[8][4];
    #pragma unroll
    for (int nt = 0; nt < 8; nt++)
        #pragma unroll
        for (int j = 0; j < 4; j++) o[nt][j] = 0.f;
    float mr[2] = {-1e30f, -1e30f};
    float lr[2] = {0.f, 0.f};

    // cooperative K/V load mapping: thread -> row cr, 16 cols at cc
    const int cr = tid >> 2;
    const int cc = (tid & 3) << 4;

    float4 pk[4], pv[4];
    #pragma unroll
    for (int u = 0; u < 4; u++) {
        pk[u] = *(const float4*)&Kg[(size_t)cr * HD + cc + 4 * u];
        pv[u] = *(const float4*)&Vg[(size_t)cr * HD + cc + 4 * u];
    }

    for (int kt = 0; kt < Sq / 64; kt++) {
        const int k0 = kt * 64;

        // store prefetched tile (convert to tf32)
        #pragma unroll
        for (int u = 0; u < 4; u++) {
            float4 t;
            t.x = __uint_as_float(f2tf(pk[u].x)); t.y = __uint_as_float(f2tf(pk[u].y));
            t.z = __uint_as_float(f2tf(pk[u].z)); t.w = __uint_as_float(f2tf(pk[u].w));
            *(float4*)&Ks[cr][cc + 4 * u] = t;
            t.x = __uint_as_float(f2tf(pv[u].x)); t.y = __uint_as_float(f2tf(pv[u].y));
            t.z = __uint_as_float(f2tf(pv[u].z)); t.w = __uint_as_float(f2tf(pv[u].w));
            *(float4*)&Vs[cr][cc + 4 * u] = t;
        }
        __syncthreads();

        // prefetch next tile (overlaps compute)
        if (kt + 1 < Sq / 64) {
            const int kn = (kt + 1) * 64;
            #pragma unroll
            for (int u = 0; u < 4; u++) {
                pk[u] = *(const float4*)&Kg[(size_t)(kn + cr) * HD + cc + 4 * u];
                pv[u] = *(const float4*)&Vg[(size_t)(kn + cr) * HD + cc + 4 * u];
            }
        }

        // S = Q K^T (tensor cores)
        float s[8][4];
        #pragma unroll
        for (int nt = 0; nt < 8; nt++)
            #pragma unroll
            for (int j = 0; j < 4; j++) s[nt][j] = 0.f;

        #pragma unroll
        for (int ks = 0; ks < 8; ks++) {
            #pragma unroll
            for (int nt = 0; nt < 8; nt++) {
                const int krow = lg + 8 * nt;
                unsigned bb[2];
                bb[0] = __float_as_uint(Ks[krow][8 * ks + lt    ]);
                bb[1] = __float_as_uint(Ks[krow][8 * ks + lt + 4]);
                mma_tf32(s[nt], qa[ks], bb);
            }
        }

        // masks (fp32)
        #pragma unroll
        for (int nt = 0; nt < 8; nt++) {
            const float2 amv = *(const float2*)&am[(size_t)b * Sq + k0 + 8 * nt + 2 * lt];
            #pragma unroll
            for (int i = 0; i < 2; i++) {
                const int qg = qr + 8 * i;
                const float2 dmv =
                    *(const float2*)&dm[((size_t)b * Sq + qg) * Sq + k0 + 8 * nt + 2 * lt];
                s[nt][2 * i    ] += amv.x + dmv.x;
                s[nt][2 * i + 1] += amv.y + dmv.y;
            }
        }

        // online softmax (registers + 4-lane shuffles)
        float mx[2] = {-1e30f, -1e30f};
        #pragma unroll
        for (int nt = 0; nt < 8; nt++) {
            mx[0] = fmaxf(mx[0], fmaxf(s[nt][0], s[nt][1]));
            mx[1] = fmaxf(mx[1], fmaxf(s[nt][2], s[nt][3]));
        }
        float al[2];
        #pragma unroll
        for (int i = 0; i < 2; i++) {
            mx[i] = fmaxf(mx[i], __shfl_xor_sync(0xffffffffu, mx[i], 1));
            mx[i] = fmaxf(mx[i], __shfl_xor_sync(0xffffffffu, mx[i], 2));
            const float mn = fmaxf(mr[i], mx[i]);
            al[i] = __expf(mr[i] - mn);
            mr[i] = mn;
        }
        float sum[2] = {0.f, 0.f};
        #pragma unroll
        for (int nt = 0; nt < 8; nt++) {
            #pragma unroll
            for (int i = 0; i < 2; i++) {
                const float p0 = __expf(s[nt][2 * i    ] - mr[i]);
                const float p1 = __expf(s[nt][2 * i + 1] - mr[i]);
                sum[i] += p0 + p1;
                float2 pt;
                pt.x = __uint_as_float(f2tf(p0));
                pt.y = __uint_as_float(f2tf(p1));
                *(float2*)&Ps[pr + 8 * i][8 * nt + 2 * lt] = pt;
            }
        }
        #pragma unroll
        for (int i = 0; i < 2; i++) {
            sum[i] += __shfl_xor_sync(0xffffffffu, sum[i], 1);
            sum[i] += __shfl_xor_sync(0xffffffffu, sum[i], 2);
            lr[i] = lr[i] * al[i] + sum[i];
        }
        #pragma unroll
        for (int nt = 0; nt < 8; nt++) {
            o[nt][0] *= al[0]; o[nt][1] *= al[0];
            o[nt][2] *= al[1]; o[nt][3] *= al[1];
        }
        __syncwarp();

        // O += P V (tensor cores); Ps rows are warp-private
        #pragma unroll
        for (int ks = 0; ks < 8; ks++) {
            unsigned a2[4];
            a2[0] = __float_as_uint(Ps[pr    ][8 * ks + lt    ]);
            a2[1] = __float_as_uint(Ps[pr + 8][8 * ks + lt    ]);
            a2[2] = __float_as_uint(Ps[pr    ][8 * ks + lt + 4]);
            a2[3] = __float_as_uint(Ps[pr + 8][8 * ks + lt + 4]);
            #pragma unroll
            for (int nt = 0; nt < 8; nt++) {
                unsigned bb[2];
                bb[0] = __float_as_uint(Vs[8 * ks + lt    ][8 * nt + lg]);
                bb[1] = __float_as_uint(Vs[8 * ks + lt + 4][8 * nt + lg]);
                mma_tf32(o[nt], a2, bb);
            }
        }
        __syncthreads();
    }

    // normalize + write out[b][q][h*64 + d]
    float inv[2];
    inv[0] = 1.0f / lr[0];
    inv[1] = 1.0f / lr[1];
    #pragma unroll
    for (int nt = 0; nt < 8; nt++) {
        #pragma unroll
        for (int i = 0; i < 2; i++) {
            const int qg = qr + 8 * i;
            float2 r;
            r.x = o[nt][2 * i    ] * inv[i];
            r.y = o[nt][2 * i + 1] * inv[i];
            *(float2*)&out[((size_t)b * Sq + qg) * Emb + h * HD + 8 * nt + 2 * lt] = r;
        }
    }
}

// ---------------------------------------------------------------------------
extern "C" void kernel_launch(void* const* d_in, const int* in_sizes, int n_in,
                              void* d_out, int out_size)
{
    const float* X  = (const float*)d_in[0];
    const float* am = (const float*)d_in[1];
    const float* dm = (const float*)d_in[2];
    const float* Wq = (const float*)d_in[3];
    const float* bq = (const float*)d_in[4];
    const float* Wk = (const float*)d_in[5];
    const float* bk = (const float*)d_in[6];
    const float* Wv = (const float*)d_in[7];
    const float* bv = (const float*)d_in[8];
    float* out = (float*)d_out;

    qkv_kernel<<<dim3(18, 64), 256>>>(X, Wq, bq, Wk, bk, Wv, bv);

    cudaFuncSetAttribute(attn_kernel,
                         cudaFuncAttributeMaxDynamicSharedMemorySize,
                         ATTN_SMEM);
    attn_kernel<<<dim3(Sq / 128, NH, Bsz), 256, ATTN_SMEM>>>(am, dm, out);
}